// round 7
// baseline (speedup 1.0000x reference)
#include <cuda_runtime.h>
#include <math.h>

#define BT 128
#define HWPX 16384
#define WF 65
#define NYK 8320   // 128*65

__device__ float  d_z1[BT*16*HWPX];
__device__ float  d_ga[BT*16*HWPX];
__device__ float  d_gb[BT*16*HWPX];
__device__ float  d_Xt[BT*8*HWPX];
__device__ float2 d_S [1024*NYK];
__device__ float2 d_S2[1024*NYK];
__device__ float  d_omega[NYK*8];
__device__ float  d_scale[BT];

__device__ __forceinline__ float sg_(float z){ return 1.f/(1.f+__expf(-z)); }
__device__ __forceinline__ float silu_(float z){ return z*sg_(z); }
__device__ __forceinline__ float silup_(float z){ float s=sg_(z); return s+z*s*(1.f-s); }
__device__ __forceinline__ float2 cadd2(float2 a,float2 b){ return make_float2(a.x+b.x,a.y+b.y); }
__device__ __forceinline__ float2 csub2(float2 a,float2 b){ return make_float2(a.x-b.x,a.y-b.y); }
__device__ __forceinline__ float2 cmul2(float2 a,float2 b){ return make_float2(fmaf(a.x,b.x,-(a.y*b.y)),fmaf(a.x,b.y,a.y*b.x)); }
template<int S> __device__ __forceinline__ float2 rotmi(float2 a){ return (S>0)?make_float2(a.y,-a.x):make_float2(-a.y,a.x); }

template<int S> __device__ __forceinline__ void dft4(float2&x0,float2&x1,float2&x2,float2&x3){
    float2 t0=cadd2(x0,x2),t1=csub2(x0,x2),t2=cadd2(x1,x3),t3=csub2(x1,x3);
    x0=cadd2(t0,t2); x2=csub2(t0,t2); float2 r=rotmi<S>(t3); x1=cadd2(t1,r); x3=csub2(t1,r);
}
template<int S> __device__ __forceinline__ void dft8(float2 a[8]){
    float2 e0=a[0],e1=a[2],e2=a[4],e3=a[6],o0=a[1],o1=a[3],o2=a[5],o3=a[7];
    dft4<S>(e0,e1,e2,e3); dft4<S>(o0,o1,o2,o3);
    const float c8=0.70710678118654752f; float2 w1o,w3o;
    if(S>0){ w1o=make_float2(c8*(o1.x+o1.y),c8*(o1.y-o1.x)); w3o=make_float2(c8*(o3.y-o3.x),-c8*(o3.x+o3.y)); }
    else   { w1o=make_float2(c8*(o1.x-o1.y),c8*(o1.y+o1.x)); w3o=make_float2(-c8*(o3.x+o3.y),c8*(o3.x-o3.y)); }
    float2 w2o=rotmi<S>(o2);
    a[0]=cadd2(e0,o0); a[4]=csub2(e0,o0); a[1]=cadd2(e1,w1o); a[5]=csub2(e1,w1o);
    a[2]=cadd2(e2,w2o); a[6]=csub2(e2,w2o); a[3]=cadd2(e3,w3o); a[7]=csub2(e3,w3o);
}
template<int S> __device__ __forceinline__ void dft16(float2 b[16]){
    float2 e[8],o[8];
#pragma unroll
    for(int r=0;r<8;r++){ e[r]=b[2*r]; o[r]=b[2*r+1]; }
    dft8<S>(e); dft8<S>(o);
    const float CW[8]={1.f,0.92387953251128674f,0.70710678118654752f,0.38268343236508977f,0.f,-0.38268343236508977f,-0.70710678118654752f,-0.92387953251128674f};
    const float SW[8]={0.f,0.38268343236508977f,0.70710678118654752f,0.92387953251128674f,1.f,0.92387953251128674f,0.70710678118654752f,0.38268343236508977f};
#pragma unroll
    for(int m=0;m<8;m++){
        float2 w=make_float2(CW[m],(S>0)?-SW[m]:SW[m]);
        float2 wo=cmul2(o[m],w); b[m]=cadd2(e[m],wo); b[m+8]=csub2(e[m],wo);
    }
}
template<int S> __device__ __forceinline__ void fft128(float2 x[8],float2 out[16],int t,float2* wbuf,const float2* tw){
    dft8<S>(x);
#pragma unroll
    for(int k=0;k<8;k++){
        float2 v;
        if(k==0) v=x[0];
        else { float2 w=tw[t*k]; if(S<0) w.y=-w.y; v=cmul2(x[k],w); }
        wbuf[k*17+t]=v;
    }
    __syncthreads();
    if(t<8){
        float2 b[16];
#pragma unroll
        for(int m=0;m<16;m++) b[m]=wbuf[t*17+m];
        dft16<S>(b);
#pragma unroll
        for(int m=0;m<16;m++) out[m]=b[m];
    }
}
__device__ __forceinline__ void build_tw(float2* tw,int tid){
    if(tid<128){ float s,c; sincosf(-6.283185307179586477f*(float)tid/128.f,&s,&c); tw[tid]=make_float2(c,s); }
}

// All-channel smem tile conv: ONE barrier per block, uninterrupted FMA stream.
// MODE 0: z1=conv1(x)+b1 | 1: g2=s2*silu'(conv2(silu(z1))+b2) | 2: conv2T(g2)*silu'(z1) | 3: x+dt*conv1T(gb)
template<int CI,int CO,int MODE>
__global__ void __launch_bounds__(256,2) k_conv(const float* __restrict__ in,float* __restrict__ out,
        const float* __restrict__ w,const float* __restrict__ bias,
        const float* __restrict__ aux1,const float* __restrict__ aux2){
    extern __shared__ float sm[];
    float* sin_=sm;                    // CI*18*68
    float* sw  =sm+CI*18*68;           // CI*CO*9
    float* sb  =sw+CI*CO*9;            // 16
    float* s2s =sb+16;                 // 16
    const int tid=threadIdx.x;
    const int tx=tid&63, ty=tid>>6;    // 64 x 4 threads; 4 rows/thread
    const int img=blockIdx.z;
    const int gx0=blockIdx.x*64, gy0=blockIdx.y*16;
    for(int idx=tid; idx<CI*CO*9; idx+=256){
        if(MODE<=1){ int o=idx/(CI*9), r=idx%(CI*9), ci=r/9, k=r%9; sw[(ci*CO+o)*9+k]=w[idx]; }
        else { int i=idx/9, k=idx%9; sw[i*9+(8-k)]=w[idx]; }
    }
    if(MODE<=1){ if(tid<CO) sb[tid]=bias[tid]; }
    if(MODE==1){ if(tid<CO){ float s=0.f; for(int oo=0;oo<8;oo++) s+=aux1[oo*16+tid]; s2s[tid]=s; } }
    // full CI-channel halo tile, loaded once
    for(int idx=tid; idx<CI*18*66; idx+=256){
        int ci=idx/(18*66); int rem=idx-ci*(18*66); int r=rem/66, c=rem-r*66;
        int gy=gy0+r-1, gx=gx0+c-1; float v=0.f;
        if(gy>=0&&gy<128&&gx>=0&&gx<128){
            v=in[((size_t)img*CI+ci)*HWPX+gy*128+gx];
            if(MODE==1) v=silu_(v);
        }
        sin_[(ci*18+r)*68+c]=v;
    }
    __syncthreads();
    float acc[CO][4];
#pragma unroll
    for(int o=0;o<CO;o++)
#pragma unroll
        for(int q=0;q<4;q++) acc[o][q]=0.f;
    const int r0=ty*4;
    for(int ci=0;ci<CI;ci++){
        const float* tp=sin_+ci*18*68;
        float v[6][3];
#pragma unroll
        for(int rr=0;rr<6;rr++)
#pragma unroll
            for(int ss=0;ss<3;ss++) v[rr][ss]=tp[(r0+rr)*68+tx+ss];
        const float* swci=&sw[ci*CO*9];
#pragma unroll
        for(int o=0;o<CO;o++){
            const float* wo=swci+o*9;
            float w0=wo[0],w1=wo[1],w2=wo[2],w3=wo[3],w4=wo[4],w5=wo[5],w6=wo[6],w7=wo[7],w8=wo[8];
#pragma unroll
            for(int q=0;q<4;q++){
                float a=acc[o][q];
                a=fmaf(w0,v[q][0],a);   a=fmaf(w1,v[q][1],a);   a=fmaf(w2,v[q][2],a);
                a=fmaf(w3,v[q+1][0],a); a=fmaf(w4,v[q+1][1],a); a=fmaf(w5,v[q+1][2],a);
                a=fmaf(w6,v[q+2][0],a); a=fmaf(w7,v[q+2][1],a); a=fmaf(w8,v[q+2][2],a);
                acc[o][q]=a;
            }
        }
    }
    const int xg=gx0+tx;
    float dtb=0.f; if(MODE==3) dtb=aux2[img>>5];
#pragma unroll
    for(int o=0;o<CO;o++)
#pragma unroll
        for(int q=0;q<4;q++){
            int y=gy0+r0+q;
            size_t oi=((size_t)img*CO+o)*HWPX+y*128+xg;
            float a=acc[o][q];
            if(MODE==0) out[oi]=a+sb[o];
            else if(MODE==1){ float z2=a+sb[o]; out[oi]=s2s[o]*silup_(z2); }
            else if(MODE==2){ out[oi]=a*silup_(aux1[((size_t)img*16+o)*HWPX+y*128+xg]); }
            else out[oi]=aux1[((size_t)img*8+o)*HWPX+y*128+xg]+dtb*a;
        }
}

__global__ void k_omega(const float* w1,const float* b1,const float* w2,const float* b2){
    int iy=threadIdx.x, ix=blockIdx.x;
    float ky=(iy<64?(float)iy:(float)(iy-128))*(1.f/128.f), kx=(float)ix*(1.f/128.f);
    float acc[8];
#pragma unroll
    for(int c=0;c<8;c++) acc[c]=0.f;
    for(int h=0;h<64;h++){
        float hid=silu_(fmaf(ky,w1[h],fmaf(kx,w1[64+h],b1[h])));
#pragma unroll
        for(int c=0;c<8;c++) acc[c]=fmaf(hid,w2[h*8+c],acc[c]);
    }
    float kp=sqrtf(ky*ky+kx*kx);
#pragma unroll
    for(int c=0;c<8;c++) d_omega[(iy*WF+ix)*8+c]=acc[c]+b2[c]+kp;
}

__global__ void __launch_bounds__(256) k_fwd_x(const float* __restrict__ xt){
    __shared__ float2 tw[128]; __shared__ float2 swork[16][136]; __shared__ float2 sZ[16][128];
    int tid=threadIdx.x; build_tw(tw,tid); __syncthreads();
    int g=tid>>4, t=tid&15, gid=blockIdx.x*16+g, IC=gid>>6, p=gid&63;
    const float* r0=xt+(size_t)IC*HWPX+(size_t)(2*p)*128; const float* r1=r0+128;
    float2 x[8];
#pragma unroll
    for(int j=0;j<8;j++){ int n=t+16*j; x[j]=make_float2(r0[n],r1[n]); }
    float2 out[16]; fft128<1>(x,out,t,swork[g],tw);
    if(t<8){
#pragma unroll
        for(int m=0;m<16;m++) sZ[g][t+8*m]=out[m];
    }
    __syncthreads();
    float2* Sp=d_S+(size_t)IC*NYK+(size_t)(2*p)*WF;
    for(int k=t;k<=64;k+=16){
        float2 P=sZ[g][k], Q=sZ[g][(128-k)&127];
        Sp[k]   =make_float2(0.5f*(P.x+Q.x),0.5f*(P.y-Q.y));
        Sp[WF+k]=make_float2(0.5f*(P.y+Q.y),0.5f*(Q.x-P.x));
    }
}

template<int DIR>
__global__ void __launch_bounds__(256) k_fft_y(int buf){
    __shared__ float2 tw[128]; __shared__ float2 tile[128*17]; __shared__ float2 swork[16][136];
    int tid=threadIdx.x; build_tw(tw,tid);
    int IC=blockIdx.y, k0=blockIdx.x*16;
    float2* Sp=(buf?d_S2:d_S)+(size_t)IC*NYK;
    __syncthreads();
    for(int idx=tid; idx<2048; idx+=256){
        int y=idx>>4, gg=idx&15, k=k0+gg; if(k>64)k=64;
        tile[y*17+gg]=Sp[y*WF+k];
    }
    __syncthreads();
    int g=tid>>4, t=tid&15;
    float sc=(DIR>0)?(1.f/128.f):(d_scale[IC>>3]*(1.f/128.f));
    float2 x[8];
#pragma unroll
    for(int j=0;j<8;j++){
        float2 v=tile[(t+16*j)*17+g];
        if(DIR<0){ v.x*=sc; v.y*=sc; }
        x[j]=v;
    }
    float2 out[16]; fft128<DIR>(x,out,t,swork[g],tw);
    __syncthreads();
    if(t<8){
#pragma unroll
        for(int m=0;m<16;m++){
            float2 v=out[m]; if(DIR>0){ v.x*=sc; v.y*=sc; }
            tile[(t+8*m)*17+g]=v;
        }
    }
    __syncthreads();
    int ncol=65-k0; if(ncol>16)ncol=16;
    for(int idx=tid; idx<2048; idx+=256){
        int y=idx>>4, gg=idx&15;
        if(gg<ncol) Sp[y*WF+(k0+gg)]=tile[y*17+gg];
    }
}

__global__ void k_project(int buf){
    int e=blockIdx.x*256+threadIdx.x; if(e>=BT*NYK) return;
    int IMG=e/NYK, yk=e%NYK, y=yk/WF, k=yk%WF;
    float gky=(y<64?(float)y:(float)(y-128))*(1.f/128.f), gkx=(float)k*(1.f/128.f);
    float k2=gky*gky+gkx*gkx; if(y==0&&k==0) k2=1.f;
    float2* S=buf?d_S2:d_S;
    float2* U=S+(size_t)(IMG*8+0)*NYK+yk; float2* V=S+(size_t)(IMG*8+1)*NYK+yk;
    float2 u=*U, v=*V;
    float dr=(gky*u.x+gkx*v.x)/k2, di=(gky*u.y+gkx*v.y)/k2;
    *U=make_float2(u.x-gky*dr,u.y-gky*di);
    *V=make_float2(v.x-gkx*dr,v.y-gkx*di);
}

__global__ void k_scan(const float* __restrict__ dt){
    int e=blockIdx.x*256+threadIdx.x; if(e>=4*8*NYK) return;
    int b=e/(8*NYK), r=e%(8*NYK), c=r/NYK, yk=r%NYK;
    float ph=d_omega[yk*8+c]*dt[b];
    float sa,ca; sincosf(ph,&sa,&ca);
    float2 A=make_float2(ca,sa), h=make_float2(0.f,0.f);
    const float2* Xp=d_S+(size_t)(b*32*8+c)*NYK+yk;
    float2* Hp=d_S2+(size_t)(b*32*8+c)*NYK+yk;
    for(int t=0;t<32;t++){
        float2 X=Xp[(size_t)t*8*NYK];
        h=cadd2(cmul2(A,h),X);
        Hp[(size_t)t*8*NYK]=h;
    }
}

__global__ void __launch_bounds__(256) k_norm(){
    int IMG=blockIdx.x, tid=threadIdx.x;
    size_t base=(size_t)IMG*8*NYK;
    float s1=0.f,s2=0.f;
    for(int i=tid;i<8*NYK;i+=256){
        float2 a=d_S[base+i];  s1=fmaf(a.x,a.x,fmaf(a.y,a.y,s1));
        float2 h=d_S2[base+i]; s2=fmaf(h.x,h.x,fmaf(h.y,h.y,s2));
    }
#pragma unroll
    for(int o=16;o;o>>=1){ s1+=__shfl_down_sync(~0u,s1,o); s2+=__shfl_down_sync(~0u,s2,o); }
    __shared__ float r1[8],r2[8];
    if((tid&31)==0){ r1[tid>>5]=s1; r2[tid>>5]=s2; }
    __syncthreads();
    if(tid==0){
        float a=0.f,bb=0.f;
        for(int w=0;w<8;w++){ a+=r1[w]; bb+=r2[w]; }
        d_scale[IMG]=sqrtf(a)/(sqrtf(bb)+1e-6f);
    }
}

__global__ void __launch_bounds__(256) k_inv_x(float* __restrict__ out){
    __shared__ float2 tw[128]; __shared__ float2 swork[16][136]; __shared__ float2 ssp[16][2][66];
    int tid=threadIdx.x; build_tw(tw,tid);
    int g=tid>>4, t=tid&15, gid=blockIdx.x*16+g, IC=gid>>6, p=gid&63;
    const float2* Sp=d_S2+(size_t)IC*NYK+(size_t)(2*p)*WF;
    for(int k=t;k<=64;k+=16){
        float2 a=Sp[k], b=Sp[WF+k];
        if(k==0||k==64){ a.y=0.f; b.y=0.f; }
        ssp[g][0][k]=a; ssp[g][1][k]=b;
    }
    __syncthreads();
    float2 x[8];
#pragma unroll
    for(int j=0;j<8;j++){
        int n=t+16*j;
        float2 Z;
        if(n<=64){ float2 a=ssp[g][0][n], b=ssp[g][1][n]; Z=make_float2(a.x-b.y,a.y+b.x); }
        else { int n2=128-n; float2 a=ssp[g][0][n2], b=ssp[g][1][n2]; Z=make_float2(a.x+b.y,b.x-a.y); }
        x[j]=Z;
    }
    float2 o16[16]; fft128<-1>(x,o16,t,swork[g],tw);
    if(t<8){
        float* base=out+(size_t)IC*HWPX;
#pragma unroll
        for(int m=0;m<16;m++){
            int n=t+8*m;
            base[(2*p)*128+n]  =o16[m].x;
            base[(2*p+1)*128+n]=o16[m].y;
        }
    }
}

extern "C" void kernel_launch(void* const* d_in,const int* in_sizes,int n_in,void* d_out,int out_size){
    const float* x  =(const float*)d_in[0];
    const float* dt =(const float*)d_in[1];
    const float* pw1=(const float*)d_in[2];
    const float* pb1=(const float*)d_in[3];
    const float* pw2=(const float*)d_in[4];
    const float* pb2=(const float*)d_in[5];
    const float* w1 =(const float*)d_in[6];
    const float* b1 =(const float*)d_in[7];
    const float* w2 =(const float*)d_in[8];
    const float* b2 =(const float*)d_in[9];
    const float* w3 =(const float*)d_in[10];

    const int sm0=(8*18*68+8*16*9+32)*4;
    const int sm1=(16*18*68+16*16*9+32)*4;
    const int sm3=(16*18*68+16*8*9+32)*4;
    cudaFuncSetAttribute(k_conv<8,16,0>,  cudaFuncAttributeMaxDynamicSharedMemorySize, sm0);
    cudaFuncSetAttribute(k_conv<16,16,1>, cudaFuncAttributeMaxDynamicSharedMemorySize, sm1);
    cudaFuncSetAttribute(k_conv<16,16,2>, cudaFuncAttributeMaxDynamicSharedMemorySize, sm1);
    cudaFuncSetAttribute(k_conv<16,8,3>,  cudaFuncAttributeMaxDynamicSharedMemorySize, sm3);

    dim3 cg(2,8,128);
    k_conv<8,16,0><<<cg,256,sm0>>>(x,   d_z1,w1,b1,nullptr,nullptr);
    k_conv<16,16,1><<<cg,256,sm1>>>(d_z1,d_ga,w2,b2,w3,nullptr);
    k_conv<16,16,2><<<cg,256,sm1>>>(d_ga,d_gb,w2,nullptr,d_z1,nullptr);
    k_conv<16,8,3><<<cg,256,sm3>>>(d_gb,d_Xt,w1,nullptr,x,dt);
    k_omega<<<65,128>>>(pw1,pb1,pw2,pb2);
    k_fwd_x<<<4096,256>>>(d_Xt);
    k_fft_y<1><<<dim3(5,1024),256>>>(0);
    k_project<<<4160,256>>>(0);
    k_scan<<<1040,256>>>(dt);
    k_project<<<4160,256>>>(1);
    k_norm<<<128,256>>>();
    k_fft_y<-1><<<dim3(5,1024),256>>>(1);
    k_inv_x<<<4096,256>>>((float*)d_out);
}

// round 8
// speedup vs baseline: 1.0447x; 1.0447x over previous
#include <cuda_runtime.h>
#include <math.h>

#define BT 128
#define HWPX 16384
#define WF 65
#define NYK 8320   // 128*65

__device__ float  d_z1[BT*16*HWPX];
__device__ float  d_ga[BT*16*HWPX];
__device__ float  d_gb[BT*16*HWPX];
__device__ float  d_Xt[BT*8*HWPX];
__device__ float2 d_S [1024*NYK];
__device__ float2 d_S2[1024*NYK];
__device__ float  d_omega[NYK*8];
__device__ float  d_scale[BT];

__device__ __forceinline__ float sg_(float z){ return 1.f/(1.f+__expf(-z)); }
__device__ __forceinline__ float silu_(float z){ return z*sg_(z); }
__device__ __forceinline__ float silup_(float z){ float s=sg_(z); return s+z*s*(1.f-s); }
__device__ __forceinline__ float2 cadd2(float2 a,float2 b){ return make_float2(a.x+b.x,a.y+b.y); }
__device__ __forceinline__ float2 csub2(float2 a,float2 b){ return make_float2(a.x-b.x,a.y-b.y); }
__device__ __forceinline__ float2 cmul2(float2 a,float2 b){ return make_float2(fmaf(a.x,b.x,-(a.y*b.y)),fmaf(a.x,b.y,a.y*b.x)); }
template<int S> __device__ __forceinline__ float2 rotmi(float2 a){ return (S>0)?make_float2(a.y,-a.x):make_float2(-a.y,a.x); }

template<int S> __device__ __forceinline__ void dft4(float2&x0,float2&x1,float2&x2,float2&x3){
    float2 t0=cadd2(x0,x2),t1=csub2(x0,x2),t2=cadd2(x1,x3),t3=csub2(x1,x3);
    x0=cadd2(t0,t2); x2=csub2(t0,t2); float2 r=rotmi<S>(t3); x1=cadd2(t1,r); x3=csub2(t1,r);
}
template<int S> __device__ __forceinline__ void dft8(float2 a[8]){
    float2 e0=a[0],e1=a[2],e2=a[4],e3=a[6],o0=a[1],o1=a[3],o2=a[5],o3=a[7];
    dft4<S>(e0,e1,e2,e3); dft4<S>(o0,o1,o2,o3);
    const float c8=0.70710678118654752f; float2 w1o,w3o;
    if(S>0){ w1o=make_float2(c8*(o1.x+o1.y),c8*(o1.y-o1.x)); w3o=make_float2(c8*(o3.y-o3.x),-c8*(o3.x+o3.y)); }
    else   { w1o=make_float2(c8*(o1.x-o1.y),c8*(o1.y+o1.x)); w3o=make_float2(-c8*(o3.x+o3.y),c8*(o3.x-o3.y)); }
    float2 w2o=rotmi<S>(o2);
    a[0]=cadd2(e0,o0); a[4]=csub2(e0,o0); a[1]=cadd2(e1,w1o); a[5]=csub2(e1,w1o);
    a[2]=cadd2(e2,w2o); a[6]=csub2(e2,w2o); a[3]=cadd2(e3,w3o); a[7]=csub2(e3,w3o);
}
template<int S> __device__ __forceinline__ void dft16(float2 b[16]){
    float2 e[8],o[8];
#pragma unroll
    for(int r=0;r<8;r++){ e[r]=b[2*r]; o[r]=b[2*r+1]; }
    dft8<S>(e); dft8<S>(o);
    const float CW[8]={1.f,0.92387953251128674f,0.70710678118654752f,0.38268343236508977f,0.f,-0.38268343236508977f,-0.70710678118654752f,-0.92387953251128674f};
    const float SW[8]={0.f,0.38268343236508977f,0.70710678118654752f,0.92387953251128674f,1.f,0.92387953251128674f,0.70710678118654752f,0.38268343236508977f};
#pragma unroll
    for(int m=0;m<8;m++){
        float2 w=make_float2(CW[m],(S>0)?-SW[m]:SW[m]);
        float2 wo=cmul2(o[m],w); b[m]=cadd2(e[m],wo); b[m+8]=csub2(e[m],wo);
    }
}
template<int S> __device__ __forceinline__ void fft128(float2 x[8],float2 out[16],int t,float2* wbuf,const float2* tw){
    dft8<S>(x);
#pragma unroll
    for(int k=0;k<8;k++){
        float2 v;
        if(k==0) v=x[0];
        else { float2 w=tw[t*k]; if(S<0) w.y=-w.y; v=cmul2(x[k],w); }
        wbuf[k*17+t]=v;
    }
    __syncthreads();
    if(t<8){
        float2 b[16];
#pragma unroll
        for(int m=0;m<16;m++) b[m]=wbuf[t*17+m];
        dft16<S>(b);
#pragma unroll
        for(int m=0;m<16;m++) out[m]=b[m];
    }
}
__device__ __forceinline__ void build_tw(float2* tw,int tid){
    if(tid<128){ float s,c; sincosf(-6.283185307179586477f*(float)tid/128.f,&s,&c); tw[tid]=make_float2(c,s); }
}

// All-channel smem tile conv with REGISTER WEIGHT PREFETCH (hides LDS latency).
// MODE 0: z1=conv1(x)+b1 | 1: g2=s2*silu'(conv2(silu(z1))+b2) | 2: conv2T(g2)*silu'(z1) | 3: x+dt*conv1T(gb)
template<int CI,int CO,int MODE>
__global__ void __launch_bounds__(256,2) k_conv(const float* __restrict__ in,float* __restrict__ out,
        const float* __restrict__ w,const float* __restrict__ bias,
        const float* __restrict__ aux1,const float* __restrict__ aux2){
    extern __shared__ float sm[];
    float* sin_=sm;                    // CI*18*68
    float* sw  =sm+CI*18*68;           // CI*CO*9
    float* sb  =sw+CI*CO*9;            // 16
    float* s2s =sb+16;                 // 16
    const int tid=threadIdx.x;
    const int tx=tid&63, ty=tid>>6;    // 64 x 4 threads; 4 rows/thread
    const int img=blockIdx.z;
    const int gx0=blockIdx.x*64, gy0=blockIdx.y*16;
    for(int idx=tid; idx<CI*CO*9; idx+=256){
        if(MODE<=1){ int o=idx/(CI*9), r=idx%(CI*9), ci=r/9, k=r%9; sw[(ci*CO+o)*9+k]=w[idx]; }
        else { int i=idx/9, k=idx%9; sw[i*9+(8-k)]=w[idx]; }
    }
    if(MODE<=1){ if(tid<CO) sb[tid]=bias[tid]; }
    if(MODE==1){ if(tid<CO){ float s=0.f; for(int oo=0;oo<8;oo++) s+=aux1[oo*16+tid]; s2s[tid]=s; } }
    for(int idx=tid; idx<CI*18*66; idx+=256){
        int ci=idx/(18*66); int rem=idx-ci*(18*66); int r=rem/66, c=rem-r*66;
        int gy=gy0+r-1, gx=gx0+c-1; float v=0.f;
        if(gy>=0&&gy<128&&gx>=0&&gx<128){
            v=in[((size_t)img*CI+ci)*HWPX+gy*128+gx];
            if(MODE==1) v=silu_(v);
        }
        sin_[(ci*18+r)*68+c]=v;
    }
    __syncthreads();
    float acc[CO][4];
#pragma unroll
    for(int o=0;o<CO;o++)
#pragma unroll
        for(int q=0;q<4;q++) acc[o][q]=0.f;
    const int r0=ty*4;
    // prefetch first weight group
    float wreg[9];
#pragma unroll
    for(int k=0;k<9;k++) wreg[k]=sw[k];
    for(int ci=0;ci<CI;ci++){
        const float* tp=sin_+ci*18*68;
        float v[6][3];
#pragma unroll
        for(int rr=0;rr<6;rr++)
#pragma unroll
            for(int ss=0;ss<3;ss++) v[rr][ss]=tp[(r0+rr)*68+tx+ss];
        const int base=ci*CO*9;
#pragma unroll
        for(int o=0;o<CO;o++){
            // prefetch NEXT weight group while FMAs below run on wreg
            float wn[9];
            const float* nw = sw + ((o==CO-1)? ((ci==CI-1)?0:(base+CO*9)) : (base+(o+1)*9));
#pragma unroll
            for(int k=0;k<9;k++) wn[k]=nw[k];
#pragma unroll
            for(int q=0;q<4;q++){
                float a=acc[o][q];
                a=fmaf(wreg[0],v[q][0],a);   a=fmaf(wreg[1],v[q][1],a);   a=fmaf(wreg[2],v[q][2],a);
                a=fmaf(wreg[3],v[q+1][0],a); a=fmaf(wreg[4],v[q+1][1],a); a=fmaf(wreg[5],v[q+1][2],a);
                a=fmaf(wreg[6],v[q+2][0],a); a=fmaf(wreg[7],v[q+2][1],a); a=fmaf(wreg[8],v[q+2][2],a);
                acc[o][q]=a;
            }
#pragma unroll
            for(int k=0;k<9;k++) wreg[k]=wn[k];
        }
    }
    const int xg=gx0+tx;
    float dtb=0.f; if(MODE==3) dtb=aux2[img>>5];
#pragma unroll
    for(int o=0;o<CO;o++)
#pragma unroll
        for(int q=0;q<4;q++){
            int y=gy0+r0+q;
            size_t oi=((size_t)img*CO+o)*HWPX+y*128+xg;
            float a=acc[o][q];
            if(MODE==0) out[oi]=a+sb[o];
            else if(MODE==1){ float z2=a+sb[o]; out[oi]=s2s[o]*silup_(z2); }
            else if(MODE==2){ out[oi]=a*silup_(aux1[((size_t)img*16+o)*HWPX+y*128+xg]); }
            else out[oi]=aux1[((size_t)img*8+o)*HWPX+y*128+xg]+dtb*a;
        }
}

__global__ void k_omega(const float* w1,const float* b1,const float* w2,const float* b2){
    int iy=threadIdx.x, ix=blockIdx.x;
    float ky=(iy<64?(float)iy:(float)(iy-128))*(1.f/128.f), kx=(float)ix*(1.f/128.f);
    float acc[8];
#pragma unroll
    for(int c=0;c<8;c++) acc[c]=0.f;
    for(int h=0;h<64;h++){
        float hid=silu_(fmaf(ky,w1[h],fmaf(kx,w1[64+h],b1[h])));
#pragma unroll
        for(int c=0;c<8;c++) acc[c]=fmaf(hid,w2[h*8+c],acc[c]);
    }
    float kp=sqrtf(ky*ky+kx*kx);
#pragma unroll
    for(int c=0;c<8;c++) d_omega[(iy*WF+ix)*8+c]=acc[c]+b2[c]+kp;
}

__global__ void __launch_bounds__(256) k_fwd_x(const float* __restrict__ xt){
    __shared__ float2 tw[128]; __shared__ float2 swork[16][136]; __shared__ float2 sZ[16][128];
    int tid=threadIdx.x; build_tw(tw,tid); __syncthreads();
    int g=tid>>4, t=tid&15, gid=blockIdx.x*16+g, IC=gid>>6, p=gid&63;
    const float* r0=xt+(size_t)IC*HWPX+(size_t)(2*p)*128; const float* r1=r0+128;
    float2 x[8];
#pragma unroll
    for(int j=0;j<8;j++){ int n=t+16*j; x[j]=make_float2(r0[n],r1[n]); }
    float2 out[16]; fft128<1>(x,out,t,swork[g],tw);
    if(t<8){
#pragma unroll
        for(int m=0;m<16;m++) sZ[g][t+8*m]=out[m];
    }
    __syncthreads();
    float2* Sp=d_S+(size_t)IC*NYK+(size_t)(2*p)*WF;
    for(int k=t;k<=64;k+=16){
        float2 P=sZ[g][k], Q=sZ[g][(128-k)&127];
        Sp[k]   =make_float2(0.5f*(P.x+Q.x),0.5f*(P.y-Q.y));
        Sp[WF+k]=make_float2(0.5f*(P.y+Q.y),0.5f*(Q.x-P.x));
    }
}

template<int DIR>
__global__ void __launch_bounds__(256) k_fft_y(int buf){
    __shared__ float2 tw[128]; __shared__ float2 tile[128*17]; __shared__ float2 swork[16][136];
    int tid=threadIdx.x; build_tw(tw,tid);
    int IC=blockIdx.y, k0=blockIdx.x*16;
    float2* Sp=(buf?d_S2:d_S)+(size_t)IC*NYK;
    __syncthreads();
    for(int idx=tid; idx<2048; idx+=256){
        int y=idx>>4, gg=idx&15, k=k0+gg; if(k>64)k=64;
        tile[y*17+gg]=Sp[y*WF+k];
    }
    __syncthreads();
    int g=tid>>4, t=tid&15;
    float sc=(DIR>0)?(1.f/128.f):(d_scale[IC>>3]*(1.f/128.f));
    float2 x[8];
#pragma unroll
    for(int j=0;j<8;j++){
        float2 v=tile[(t+16*j)*17+g];
        if(DIR<0){ v.x*=sc; v.y*=sc; }
        x[j]=v;
    }
    float2 out[16]; fft128<DIR>(x,out,t,swork[g],tw);
    __syncthreads();
    if(t<8){
#pragma unroll
        for(int m=0;m<16;m++){
            float2 v=out[m]; if(DIR>0){ v.x*=sc; v.y*=sc; }
            tile[(t+8*m)*17+g]=v;
        }
    }
    __syncthreads();
    int ncol=65-k0; if(ncol>16)ncol=16;
    for(int idx=tid; idx<2048; idx+=256){
        int y=idx>>4, gg=idx&15;
        if(gg<ncol) Sp[y*WF+(k0+gg)]=tile[y*17+gg];
    }
}

__global__ void k_project(int buf){
    int e=blockIdx.x*256+threadIdx.x; if(e>=BT*NYK) return;
    int IMG=e/NYK, yk=e%NYK, y=yk/WF, k=yk%WF;
    float gky=(y<64?(float)y:(float)(y-128))*(1.f/128.f), gkx=(float)k*(1.f/128.f);
    float k2=gky*gky+gkx*gkx; if(y==0&&k==0) k2=1.f;
    float2* S=buf?d_S2:d_S;
    float2* U=S+(size_t)(IMG*8+0)*NYK+yk; float2* V=S+(size_t)(IMG*8+1)*NYK+yk;
    float2 u=*U, v=*V;
    float dr=(gky*u.x+gkx*v.x)/k2, di=(gky*u.y+gkx*v.y)/k2;
    *U=make_float2(u.x-gky*dr,u.y-gky*di);
    *V=make_float2(v.x-gkx*dr,v.y-gkx*di);
}

__global__ void k_scan(const float* __restrict__ dt){
    int e=blockIdx.x*256+threadIdx.x; if(e>=4*8*NYK) return;
    int b=e/(8*NYK), r=e%(8*NYK), c=r/NYK, yk=r%NYK;
    float ph=d_omega[yk*8+c]*dt[b];
    float sa,ca; sincosf(ph,&sa,&ca);
    float2 A=make_float2(ca,sa), h=make_float2(0.f,0.f);
    const float2* Xp=d_S+(size_t)(b*32*8+c)*NYK+yk;
    float2* Hp=d_S2+(size_t)(b*32*8+c)*NYK+yk;
    for(int t=0;t<32;t++){
        float2 X=Xp[(size_t)t*8*NYK];
        h=cadd2(cmul2(A,h),X);
        Hp[(size_t)t*8*NYK]=h;
    }
}

__global__ void __launch_bounds__(1024) k_norm(){
    int IMG=blockIdx.x, tid=threadIdx.x;
    size_t base=(size_t)IMG*8*NYK;
    float s1=0.f,s2=0.f;
    for(int i=tid;i<8*NYK;i+=1024){
        float2 a=d_S[base+i];  s1=fmaf(a.x,a.x,fmaf(a.y,a.y,s1));
        float2 h=d_S2[base+i]; s2=fmaf(h.x,h.x,fmaf(h.y,h.y,s2));
    }
#pragma unroll
    for(int o=16;o;o>>=1){ s1+=__shfl_down_sync(~0u,s1,o); s2+=__shfl_down_sync(~0u,s2,o); }
    __shared__ float r1[32],r2[32];
    if((tid&31)==0){ r1[tid>>5]=s1; r2[tid>>5]=s2; }
    __syncthreads();
    if(tid==0){
        float a=0.f,bb=0.f;
        for(int w=0;w<32;w++){ a+=r1[w]; bb+=r2[w]; }
        d_scale[IMG]=sqrtf(a)/(sqrtf(bb)+1e-6f);
    }
}

__global__ void __launch_bounds__(256) k_inv_x(float* __restrict__ out){
    __shared__ float2 tw[128]; __shared__ float2 swork[16][136]; __shared__ float2 ssp[16][2][66];
    int tid=threadIdx.x; build_tw(tw,tid);
    int g=tid>>4, t=tid&15, gid=blockIdx.x*16+g, IC=gid>>6, p=gid&63;
    const float2* Sp=d_S2+(size_t)IC*NYK+(size_t)(2*p)*WF;
    for(int k=t;k<=64;k+=16){
        float2 a=Sp[k], b=Sp[WF+k];
        if(k==0||k==64){ a.y=0.f; b.y=0.f; }
        ssp[g][0][k]=a; ssp[g][1][k]=b;
    }
    __syncthreads();
    float2 x[8];
#pragma unroll
    for(int j=0;j<8;j++){
        int n=t+16*j;
        float2 Z;
        if(n<=64){ float2 a=ssp[g][0][n], b=ssp[g][1][n]; Z=make_float2(a.x-b.y,a.y+b.x); }
        else { int n2=128-n; float2 a=ssp[g][0][n2], b=ssp[g][1][n2]; Z=make_float2(a.x+b.y,b.x-a.y); }
        x[j]=Z;
    }
    float2 o16[16]; fft128<-1>(x,o16,t,swork[g],tw);
    if(t<8){
        float* base=out+(size_t)IC*HWPX;
#pragma unroll
        for(int m=0;m<16;m++){
            int n=t+8*m;
            base[(2*p)*128+n]  =o16[m].x;
            base[(2*p+1)*128+n]=o16[m].y;
        }
    }
}

extern "C" void kernel_launch(void* const* d_in,const int* in_sizes,int n_in,void* d_out,int out_size){
    const float* x  =(const float*)d_in[0];
    const float* dt =(const float*)d_in[1];
    const float* pw1=(const float*)d_in[2];
    const float* pb1=(const float*)d_in[3];
    const float* pw2=(const float*)d_in[4];
    const float* pb2=(const float*)d_in[5];
    const float* w1 =(const float*)d_in[6];
    const float* b1 =(const float*)d_in[7];
    const float* w2 =(const float*)d_in[8];
    const float* b2 =(const float*)d_in[9];
    const float* w3 =(const float*)d_in[10];

    const int sm0=(8*18*68+8*16*9+32)*4;
    const int sm1=(16*18*68+16*16*9+32)*4;
    const int sm3=(16*18*68+16*8*9+32)*4;
    cudaFuncSetAttribute(k_conv<8,16,0>,  cudaFuncAttributeMaxDynamicSharedMemorySize, sm0);
    cudaFuncSetAttribute(k_conv<16,16,1>, cudaFuncAttributeMaxDynamicSharedMemorySize, sm1);
    cudaFuncSetAttribute(k_conv<16,16,2>, cudaFuncAttributeMaxDynamicSharedMemorySize, sm1);
    cudaFuncSetAttribute(k_conv<16,8,3>,  cudaFuncAttributeMaxDynamicSharedMemorySize, sm3);

    dim3 cg(2,8,128);
    k_conv<8,16,0><<<cg,256,sm0>>>(x,   d_z1,w1,b1,nullptr,nullptr);
    k_conv<16,16,1><<<cg,256,sm1>>>(d_z1,d_ga,w2,b2,w3,nullptr);
    k_conv<16,16,2><<<cg,256,sm1>>>(d_ga,d_gb,w2,nullptr,d_z1,nullptr);
    k_conv<16,8,3><<<cg,256,sm3>>>(d_gb,d_Xt,w1,nullptr,x,dt);
    k_omega<<<65,128>>>(pw1,pb1,pw2,pb2);
    k_fwd_x<<<4096,256>>>(d_Xt);
    k_fft_y<1><<<dim3(5,1024),256>>>(0);
    k_project<<<4160,256>>>(0);
    k_scan<<<1040,256>>>(dt);
    k_project<<<4160,256>>>(1);
    k_norm<<<128,1024>>>();
    k_fft_y<-1><<<dim3(5,1024),256>>>(1);
    k_inv_x<<<4096,256>>>((float*)d_out);
}

// round 9
// speedup vs baseline: 1.0888x; 1.0422x over previous
#include <cuda_runtime.h>
#include <math.h>

#define BT 128
#define HWPX 16384
#define WF 65
#define NYK 8320   // 128*65

__device__ float  d_z1[BT*16*HWPX];
__device__ float  d_ga[BT*16*HWPX];
__device__ float  d_gb[BT*16*HWPX];
__device__ float  d_Xt[BT*8*HWPX];
__device__ float2 d_S [1024*NYK];
__device__ float2 d_S2[1024*NYK];
__device__ float  d_omega[NYK*8];
__device__ float  d_scale[BT];

__device__ __forceinline__ float sg_(float z){ return 1.f/(1.f+__expf(-z)); }
__device__ __forceinline__ float silu_(float z){ return z*sg_(z); }
__device__ __forceinline__ float silup_(float z){ float s=sg_(z); return s+z*s*(1.f-s); }
__device__ __forceinline__ float2 cadd2(float2 a,float2 b){ return make_float2(a.x+b.x,a.y+b.y); }
__device__ __forceinline__ float2 csub2(float2 a,float2 b){ return make_float2(a.x-b.x,a.y-b.y); }
__device__ __forceinline__ float2 cmul2(float2 a,float2 b){ return make_float2(fmaf(a.x,b.x,-(a.y*b.y)),fmaf(a.x,b.y,a.y*b.x)); }
template<int S> __device__ __forceinline__ float2 rotmi(float2 a){ return (S>0)?make_float2(a.y,-a.x):make_float2(-a.y,a.x); }

template<int S> __device__ __forceinline__ void dft4(float2&x0,float2&x1,float2&x2,float2&x3){
    float2 t0=cadd2(x0,x2),t1=csub2(x0,x2),t2=cadd2(x1,x3),t3=csub2(x1,x3);
    x0=cadd2(t0,t2); x2=csub2(t0,t2); float2 r=rotmi<S>(t3); x1=cadd2(t1,r); x3=csub2(t1,r);
}
template<int S> __device__ __forceinline__ void dft8(float2 a[8]){
    float2 e0=a[0],e1=a[2],e2=a[4],e3=a[6],o0=a[1],o1=a[3],o2=a[5],o3=a[7];
    dft4<S>(e0,e1,e2,e3); dft4<S>(o0,o1,o2,o3);
    const float c8=0.70710678118654752f; float2 w1o,w3o;
    if(S>0){ w1o=make_float2(c8*(o1.x+o1.y),c8*(o1.y-o1.x)); w3o=make_float2(c8*(o3.y-o3.x),-c8*(o3.x+o3.y)); }
    else   { w1o=make_float2(c8*(o1.x-o1.y),c8*(o1.y+o1.x)); w3o=make_float2(-c8*(o3.x+o3.y),c8*(o3.x-o3.y)); }
    float2 w2o=rotmi<S>(o2);
    a[0]=cadd2(e0,o0); a[4]=csub2(e0,o0); a[1]=cadd2(e1,w1o); a[5]=csub2(e1,w1o);
    a[2]=cadd2(e2,w2o); a[6]=csub2(e2,w2o); a[3]=cadd2(e3,w3o); a[7]=csub2(e3,w3o);
}
template<int S> __device__ __forceinline__ void dft16(float2 b[16]){
    float2 e[8],o[8];
#pragma unroll
    for(int r=0;r<8;r++){ e[r]=b[2*r]; o[r]=b[2*r+1]; }
    dft8<S>(e); dft8<S>(o);
    const float CW[8]={1.f,0.92387953251128674f,0.70710678118654752f,0.38268343236508977f,0.f,-0.38268343236508977f,-0.70710678118654752f,-0.92387953251128674f};
    const float SW[8]={0.f,0.38268343236508977f,0.70710678118654752f,0.92387953251128674f,1.f,0.92387953251128674f,0.70710678118654752f,0.38268343236508977f};
#pragma unroll
    for(int m=0;m<8;m++){
        float2 w=make_float2(CW[m],(S>0)?-SW[m]:SW[m]);
        float2 wo=cmul2(o[m],w); b[m]=cadd2(e[m],wo); b[m+8]=csub2(e[m],wo);
    }
}
template<int S> __device__ __forceinline__ void fft128(float2 x[8],float2 out[16],int t,float2* wbuf,const float2* tw){
    dft8<S>(x);
#pragma unroll
    for(int k=0;k<8;k++){
        float2 v;
        if(k==0) v=x[0];
        else { float2 w=tw[t*k]; if(S<0) w.y=-w.y; v=cmul2(x[k],w); }
        wbuf[k*17+t]=v;
    }
    __syncthreads();
    if(t<8){
        float2 b[16];
#pragma unroll
        for(int m=0;m<16;m++) b[m]=wbuf[t*17+m];
        dft16<S>(b);
#pragma unroll
        for(int m=0;m<16;m++) out[m]=b[m];
    }
}
__device__ __forceinline__ void build_tw(float2* tw,int tid){
    if(tid<128){ float s,c; sincosf(-6.283185307179586477f*(float)tid/128.f,&s,&c); tw[tid]=make_float2(c,s); }
}

// Conv with float4 tile load (72-float padded rows, logical col tc stored at tc+3)
// and output-channel blocking OB=8 (acc regs halved; no spills).
// MODE 0: z1=conv1(x)+b1 | 1: g2=s2*silu'(conv2(silu(z1))+b2) | 2: conv2T(g2)*silu'(z1) | 3: x+dt*conv1T(gb)
template<int CI,int CO,int MODE>
__global__ void __launch_bounds__(256) k_conv(const float* __restrict__ in,float* __restrict__ out,
        const float* __restrict__ w,const float* __restrict__ bias,
        const float* __restrict__ aux1,const float* __restrict__ aux2){
    extern __shared__ float sm[];
    float* sin_=sm;                    // CI*18*72
    float* sw  =sm+CI*18*72;           // CI*CO*9
    float* sb  =sw+CI*CO*9;            // 16
    float* s2s =sb+16;                 // 16
    const int tid=threadIdx.x;
    const int tx=tid&63, ty=tid>>6;
    const int img=blockIdx.z;
    const int gx0=blockIdx.x*64, gy0=blockIdx.y*16;
    for(int idx=tid; idx<CI*CO*9; idx+=256){
        if(MODE<=1){ int o=idx/(CI*9), r=idx%(CI*9), ci=r/9, k=r%9; sw[(ci*CO+o)*9+k]=w[idx]; }
        else { int i=idx/9, k=idx%9; sw[i*9+(8-k)]=w[idx]; }
    }
    if(MODE<=1){ if(tid<CO) sb[tid]=bias[tid]; }
    if(MODE==1){ if(tid<CO){ float s=0.f; for(int oo=0;oo<8;oo++) s+=aux1[oo*16+tid]; s2s[tid]=s; } }
    // core: float4 loads, 16 per row (cols gx0..gx0+63 always in range)
    for(int i=tid; i<CI*288; i+=256){
        int ci=i>>8; ci=i/288; int rem=i-ci*288; int r=rem>>4, k=rem&15;
        int gy=gy0+r-1;
        float4 v4=make_float4(0.f,0.f,0.f,0.f);
        if(gy>=0&&gy<128){
            v4=*(const float4*)(in+((size_t)img*CI+ci)*HWPX+(size_t)gy*128+gx0+4*k);
            if(MODE==1){ v4.x=silu_(v4.x); v4.y=silu_(v4.y); v4.z=silu_(v4.z); v4.w=silu_(v4.w); }
        }
        *(float4*)(sin_+(size_t)(ci*18+r)*72+4+4*k)=v4;
    }
    // halo: 2 scalar cols per row
    for(int i=tid; i<CI*36; i+=256){
        int ci=i/36; int rem=i-ci*36; int r=rem>>1, side=rem&1;
        int tc=side?65:0;
        int gy=gy0+r-1, gx=gx0+tc-1;
        float v=0.f;
        if(gy>=0&&gy<128&&gx>=0&&gx<128){
            v=in[((size_t)img*CI+ci)*HWPX+(size_t)gy*128+gx];
            if(MODE==1) v=silu_(v);
        }
        sin_[(size_t)(ci*18+r)*72+tc+3]=v;
    }
    __syncthreads();
    const int r0=ty*4;
    const int xg=gx0+tx;
    float dtb=0.f; if(MODE==3) dtb=aux2[img>>5];
#pragma unroll
    for(int ob=0; ob<CO/8; ob++){
        float acc[8][4];
#pragma unroll
        for(int o8=0;o8<8;o8++)
#pragma unroll
            for(int q=0;q<4;q++) acc[o8][q]=0.f;
        for(int ci=0;ci<CI;ci++){
            const float* tp=sin_+ci*18*72;
            float v[6][3];
#pragma unroll
            for(int rr=0;rr<6;rr++)
#pragma unroll
                for(int ss=0;ss<3;ss++) v[rr][ss]=tp[(r0+rr)*72+tx+ss+3];
            const float* swci=&sw[(ci*CO+ob*8)*9];
#pragma unroll
            for(int o8=0;o8<8;o8++){
                const float* wo=swci+o8*9;
                float w0=wo[0],w1=wo[1],w2=wo[2],w3=wo[3],w4=wo[4],w5=wo[5],w6=wo[6],w7=wo[7],w8=wo[8];
#pragma unroll
                for(int q=0;q<4;q++){
                    float a=acc[o8][q];
                    a=fmaf(w0,v[q][0],a);   a=fmaf(w1,v[q][1],a);   a=fmaf(w2,v[q][2],a);
                    a=fmaf(w3,v[q+1][0],a); a=fmaf(w4,v[q+1][1],a); a=fmaf(w5,v[q+1][2],a);
                    a=fmaf(w6,v[q+2][0],a); a=fmaf(w7,v[q+2][1],a); a=fmaf(w8,v[q+2][2],a);
                    acc[o8][q]=a;
                }
            }
        }
#pragma unroll
        for(int o8=0;o8<8;o8++){
            int o=ob*8+o8;
#pragma unroll
            for(int q=0;q<4;q++){
                int y=gy0+r0+q;
                size_t oi=((size_t)img*CO+o)*HWPX+(size_t)y*128+xg;
                float a=acc[o8][q];
                if(MODE==0) out[oi]=a+sb[o];
                else if(MODE==1){ float z2=a+sb[o]; out[oi]=s2s[o]*silup_(z2); }
                else if(MODE==2){ out[oi]=a*silup_(aux1[((size_t)img*16+o)*HWPX+(size_t)y*128+xg]); }
                else out[oi]=aux1[((size_t)img*8+o)*HWPX+(size_t)y*128+xg]+dtb*a;
            }
        }
    }
}

__global__ void k_omega(const float* w1,const float* b1,const float* w2,const float* b2){
    int iy=threadIdx.x, ix=blockIdx.x;
    float ky=(iy<64?(float)iy:(float)(iy-128))*(1.f/128.f), kx=(float)ix*(1.f/128.f);
    float acc[8];
#pragma unroll
    for(int c=0;c<8;c++) acc[c]=0.f;
    for(int h=0;h<64;h++){
        float hid=silu_(fmaf(ky,w1[h],fmaf(kx,w1[64+h],b1[h])));
#pragma unroll
        for(int c=0;c<8;c++) acc[c]=fmaf(hid,w2[h*8+c],acc[c]);
    }
    float kp=sqrtf(ky*ky+kx*kx);
#pragma unroll
    for(int c=0;c<8;c++) d_omega[(iy*WF+ix)*8+c]=acc[c]+b2[c]+kp;
}

__global__ void __launch_bounds__(256) k_fwd_x(const float* __restrict__ xt){
    __shared__ float2 tw[128]; __shared__ float2 swork[16][136]; __shared__ float2 sZ[16][128];
    int tid=threadIdx.x; build_tw(tw,tid); __syncthreads();
    int g=tid>>4, t=tid&15, gid=blockIdx.x*16+g, IC=gid>>6, p=gid&63;
    const float* r0=xt+(size_t)IC*HWPX+(size_t)(2*p)*128; const float* r1=r0+128;
    float2 x[8];
#pragma unroll
    for(int j=0;j<8;j++){ int n=t+16*j; x[j]=make_float2(r0[n],r1[n]); }
    float2 out[16]; fft128<1>(x,out,t,swork[g],tw);
    if(t<8){
#pragma unroll
        for(int m=0;m<16;m++) sZ[g][t+8*m]=out[m];
    }
    __syncthreads();
    float2* Sp=d_S+(size_t)IC*NYK+(size_t)(2*p)*WF;
    for(int k=t;k<=64;k+=16){
        float2 P=sZ[g][k], Q=sZ[g][(128-k)&127];
        Sp[k]   =make_float2(0.5f*(P.x+Q.x),0.5f*(P.y-Q.y));
        Sp[WF+k]=make_float2(0.5f*(P.y+Q.y),0.5f*(Q.x-P.x));
    }
}

template<int DIR>
__global__ void __launch_bounds__(256) k_fft_y(int buf){
    __shared__ float2 tw[128]; __shared__ float2 tile[128*17]; __shared__ float2 swork[16][136];
    int tid=threadIdx.x; build_tw(tw,tid);
    int IC=blockIdx.y, k0=blockIdx.x*16;
    float2* Sp=(buf?d_S2:d_S)+(size_t)IC*NYK;
    __syncthreads();
    for(int idx=tid; idx<2048; idx+=256){
        int y=idx>>4, gg=idx&15, k=k0+gg; if(k>64)k=64;
        tile[y*17+gg]=Sp[y*WF+k];
    }
    __syncthreads();
    int g=tid>>4, t=tid&15;
    float sc=(DIR>0)?(1.f/128.f):(d_scale[IC>>3]*(1.f/128.f));
    float2 x[8];
#pragma unroll
    for(int j=0;j<8;j++){
        float2 v=tile[(t+16*j)*17+g];
        if(DIR<0){ v.x*=sc; v.y*=sc; }
        x[j]=v;
    }
    float2 out[16]; fft128<DIR>(x,out,t,swork[g],tw);
    __syncthreads();
    if(t<8){
#pragma unroll
        for(int m=0;m<16;m++){
            float2 v=out[m]; if(DIR>0){ v.x*=sc; v.y*=sc; }
            tile[(t+8*m)*17+g]=v;
        }
    }
    __syncthreads();
    int ncol=65-k0; if(ncol>16)ncol=16;
    for(int idx=tid; idx<2048; idx+=256){
        int y=idx>>4, gg=idx&15;
        if(gg<ncol) Sp[y*WF+(k0+gg)]=tile[y*17+gg];
    }
}

__global__ void k_project(int buf){
    int e=blockIdx.x*256+threadIdx.x; if(e>=BT*NYK) return;
    int IMG=e/NYK, yk=e%NYK, y=yk/WF, k=yk%WF;
    float gky=(y<64?(float)y:(float)(y-128))*(1.f/128.f), gkx=(float)k*(1.f/128.f);
    float k2=gky*gky+gkx*gkx; if(y==0&&k==0) k2=1.f;
    float2* S=buf?d_S2:d_S;
    float2* U=S+(size_t)(IMG*8+0)*NYK+yk; float2* V=S+(size_t)(IMG*8+1)*NYK+yk;
    float2 u=*U, v=*V;
    float dr=(gky*u.x+gkx*v.x)/k2, di=(gky*u.y+gkx*v.y)/k2;
    *U=make_float2(u.x-gky*dr,u.y-gky*di);
    *V=make_float2(v.x-gkx*dr,v.y-gkx*di);
}

__global__ void k_scan(const float* __restrict__ dt){
    int e=blockIdx.x*256+threadIdx.x; if(e>=4*8*NYK) return;
    int b=e/(8*NYK), r=e%(8*NYK), c=r/NYK, yk=r%NYK;
    float ph=d_omega[yk*8+c]*dt[b];
    float sa,ca; sincosf(ph,&sa,&ca);
    float2 A=make_float2(ca,sa), h=make_float2(0.f,0.f);
    const float2* Xp=d_S+(size_t)(b*32*8+c)*NYK+yk;
    float2* Hp=d_S2+(size_t)(b*32*8+c)*NYK+yk;
    for(int t=0;t<32;t++){
        float2 X=Xp[(size_t)t*8*NYK];
        h=cadd2(cmul2(A,h),X);
        Hp[(size_t)t*8*NYK]=h;
    }
}

__global__ void __launch_bounds__(1024) k_norm(){
    int IMG=blockIdx.x, tid=threadIdx.x;
    size_t base=(size_t)IMG*8*NYK;
    float s1=0.f,s2=0.f;
    for(int i=tid;i<8*NYK;i+=1024){
        float2 a=d_S[base+i];  s1=fmaf(a.x,a.x,fmaf(a.y,a.y,s1));
        float2 h=d_S2[base+i]; s2=fmaf(h.x,h.x,fmaf(h.y,h.y,s2));
    }
#pragma unroll
    for(int o=16;o;o>>=1){ s1+=__shfl_down_sync(~0u,s1,o); s2+=__shfl_down_sync(~0u,s2,o); }
    __shared__ float r1[32],r2[32];
    if((tid&31)==0){ r1[tid>>5]=s1; r2[tid>>5]=s2; }
    __syncthreads();
    if(tid==0){
        float a=0.f,bb=0.f;
        for(int w=0;w<32;w++){ a+=r1[w]; bb+=r2[w]; }
        d_scale[IMG]=sqrtf(a)/(sqrtf(bb)+1e-6f);
    }
}

__global__ void __launch_bounds__(256) k_inv_x(float* __restrict__ out){
    __shared__ float2 tw[128]; __shared__ float2 swork[16][136]; __shared__ float2 ssp[16][2][66];
    int tid=threadIdx.x; build_tw(tw,tid);
    int g=tid>>4, t=tid&15, gid=blockIdx.x*16+g, IC=gid>>6, p=gid&63;
    const float2* Sp=d_S2+(size_t)IC*NYK+(size_t)(2*p)*WF;
    for(int k=t;k<=64;k+=16){
        float2 a=Sp[k], b=Sp[WF+k];
        if(k==0||k==64){ a.y=0.f; b.y=0.f; }
        ssp[g][0][k]=a; ssp[g][1][k]=b;
    }
    __syncthreads();
    float2 x[8];
#pragma unroll
    for(int j=0;j<8;j++){
        int n=t+16*j;
        float2 Z;
        if(n<=64){ float2 a=ssp[g][0][n], b=ssp[g][1][n]; Z=make_float2(a.x-b.y,a.y+b.x); }
        else { int n2=128-n; float2 a=ssp[g][0][n2], b=ssp[g][1][n2]; Z=make_float2(a.x+b.y,b.x-a.y); }
        x[j]=Z;
    }
    float2 o16[16]; fft128<-1>(x,o16,t,swork[g],tw);
    if(t<8){
        float* base=out+(size_t)IC*HWPX;
#pragma unroll
        for(int m=0;m<16;m++){
            int n=t+8*m;
            base[(2*p)*128+n]  =o16[m].x;
            base[(2*p+1)*128+n]=o16[m].y;
        }
    }
}

extern "C" void kernel_launch(void* const* d_in,const int* in_sizes,int n_in,void* d_out,int out_size){
    const float* x  =(const float*)d_in[0];
    const float* dt =(const float*)d_in[1];
    const float* pw1=(const float*)d_in[2];
    const float* pb1=(const float*)d_in[3];
    const float* pw2=(const float*)d_in[4];
    const float* pb2=(const float*)d_in[5];
    const float* w1 =(const float*)d_in[6];
    const float* b1 =(const float*)d_in[7];
    const float* w2 =(const float*)d_in[8];
    const float* b2 =(const float*)d_in[9];
    const float* w3 =(const float*)d_in[10];

    const int sm0=(8*18*72+8*16*9+32)*4;
    const int sm1=(16*18*72+16*16*9+32)*4;
    const int sm3=(16*18*72+16*8*9+32)*4;
    cudaFuncSetAttribute(k_conv<8,16,0>,  cudaFuncAttributeMaxDynamicSharedMemorySize, sm0);
    cudaFuncSetAttribute(k_conv<16,16,1>, cudaFuncAttributeMaxDynamicSharedMemorySize, sm1);
    cudaFuncSetAttribute(k_conv<16,16,2>, cudaFuncAttributeMaxDynamicSharedMemorySize, sm1);
    cudaFuncSetAttribute(k_conv<16,8,3>,  cudaFuncAttributeMaxDynamicSharedMemorySize, sm3);

    dim3 cg(2,8,128);
    k_conv<8,16,0><<<cg,256,sm0>>>(x,   d_z1,w1,b1,nullptr,nullptr);
    k_conv<16,16,1><<<cg,256,sm1>>>(d_z1,d_ga,w2,b2,w3,nullptr);
    k_conv<16,16,2><<<cg,256,sm1>>>(d_ga,d_gb,w2,nullptr,d_z1,nullptr);
    k_conv<16,8,3><<<cg,256,sm3>>>(d_gb,d_Xt,w1,nullptr,x,dt);
    k_omega<<<65,128>>>(pw1,pb1,pw2,pb2);
    k_fwd_x<<<4096,256>>>(d_Xt);
    k_fft_y<1><<<dim3(5,1024),256>>>(0);
    k_project<<<4160,256>>>(0);
    k_scan<<<1040,256>>>(dt);
    k_project<<<4160,256>>>(1);
    k_norm<<<128,1024>>>();
    k_fft_y<-1><<<dim3(5,1024),256>>>(1);
    k_inv_x<<<4096,256>>>((float*)d_out);
}